// round 1
// baseline (speedup 1.0000x reference)
#include <cuda_runtime.h>
#include <math.h>

#define NN 100000
#define EE 1000000
#define DD 64
#define GG 128

// ---------------- scratch (device globals; no allocation allowed) ------------
__device__ float g_dinv[NN];
__device__ int   g_deg[NN];
__device__ int   g_flag[NN];
__device__ float g_temb[DD];
__device__ float g_xt[NN * DD];
__device__ float g_y[NN * GG];     // per-layer (xW)*dinv
__device__ float g_agg[NN * GG];   // per-layer edge aggregate
__device__ float g_h0[NN * GG];
__device__ float g_h1[NN * (GG / 2)];
__device__ float g_h2[NN * GG];

// ---------------- small kernels ---------------------------------------------
__global__ void k_init(int* deg, int* flag) {
    int i = blockIdx.x * blockDim.x + threadIdx.x;
    if (i < NN) { deg[i] = 0; flag[i] = 0; }
}

__global__ void k_deg(const int* __restrict__ dst, int* deg) {
    int e = blockIdx.x * blockDim.x + threadIdx.x;
    if (e < EE) atomicAdd(&deg[dst[e]], 1);
}

__global__ void k_flag(const int* __restrict__ idx, int n, int val, int* flag) {
    int i = blockIdx.x * blockDim.x + threadIdx.x;
    if (i < n) flag[idx[i]] = val;
}

// time-embedding MLP: one block, 64 threads
__global__ void k_temb(const int* __restrict__ t,
                       const float* __restrict__ w1, const float* __restrict__ b1,
                       const float* __restrict__ w2, const float* __restrict__ b2,
                       float* temb) {
    __shared__ float emb[DD];
    __shared__ float h[DD];
    int j = threadIdx.x;
    float tv = (float)t[0];
    if (j < 32) {
        float freq = expf((float)j * (-logf(10000.0f) / 31.0f));
        float arg = tv * freq;
        emb[j] = sinf(arg);
        emb[j + 32] = cosf(arg);
    }
    __syncthreads();
    float acc = b1[j];
    #pragma unroll
    for (int k = 0; k < DD; k++) acc += emb[k] * w1[k * DD + j];
    acc = acc / (1.0f + expf(-acc));   // silu
    h[j] = acc;
    __syncthreads();
    float acc2 = b2[j];
    #pragma unroll
    for (int k = 0; k < DD; k++) acc2 += h[k] * w2[k * DD + j];
    temb[j] = acc2;
}

__global__ void k_dinv(const int* __restrict__ deg, float* dinv) {
    int i = blockIdx.x * blockDim.x + threadIdx.x;
    if (i < NN) dinv[i] = rsqrtf((float)deg[i] + 1.0f);
}

// x_t = noise_x + temb + label ; vectorized float4 (D=64 -> 16 float4 per node)
__global__ void k_xt(const float* __restrict__ noise_x,
                     const float* __restrict__ label_emb,
                     const float* __restrict__ temb,
                     const int* __restrict__ flag,
                     float* __restrict__ xt) {
    int idx = blockIdx.x * blockDim.x + threadIdx.x;
    if (idx >= NN * (DD / 4)) return;
    int node = idx / (DD / 4);
    int f4 = idx % (DD / 4);
    float4 v = ((const float4*)noise_x)[idx];
    float4 tb = ((const float4*)temb)[f4];
    v.x += tb.x; v.y += tb.y; v.z += tb.z; v.w += tb.w;
    int fl = flag[node];
    if (fl == 1) {  // anm -> label_emb[1]
        float4 l = ((const float4*)(label_emb + DD))[f4];
        v.x += l.x; v.y += l.y; v.z += l.z; v.w += l.w;
    } else if (fl == 2) {  // norm -> label_emb[0]
        float4 l = ((const float4*)label_emb)[f4];
        v.x += l.x; v.y += l.y; v.z += l.z; v.w += l.w;
    }
    ((float4*)xt)[idx] = v;
}

// ---------------- GEMM: Y[row,t] (+)= (sum_k X[row,k]*W[k,t]) * dinv[row] ----
template <int FIN, int FOUT, bool ACC, bool SCALE>
__global__ void __launch_bounds__(FOUT) k_gemm(const float* __restrict__ X,
                                               const float* __restrict__ Wg,
                                               float* __restrict__ Y,
                                               const float* __restrict__ dinv) {
    constexpr int ROWS = 8;
    __shared__ float Ws[FIN * FOUT];
    __shared__ float xsT[2][FIN * 4];
    int t = threadIdx.x;
    for (int i = t; i < FIN * FOUT; i += FOUT) Ws[i] = Wg[i];
    int base = blockIdx.x * ROWS;
    for (int i = t; i < ROWS * FIN; i += FOUT) {
        int r = i / FIN, k = i % FIN;
        xsT[r >> 2][k * 4 + (r & 3)] = X[(base + r) * FIN + k];
    }
    __syncthreads();
    #pragma unroll
    for (int g = 0; g < 2; g++) {
        float a0 = 0.f, a1 = 0.f, a2 = 0.f, a3 = 0.f;
        #pragma unroll
        for (int k = 0; k < FIN; k++) {
            float w = Ws[k * FOUT + t];
            float4 xv = *(const float4*)&xsT[g][k * 4];
            a0 += xv.x * w; a1 += xv.y * w; a2 += xv.z * w; a3 += xv.w * w;
        }
        int r0 = base + g * 4;
        float s0 = SCALE ? dinv[r0 + 0] : 1.f;
        float s1 = SCALE ? dinv[r0 + 1] : 1.f;
        float s2 = SCALE ? dinv[r0 + 2] : 1.f;
        float s3 = SCALE ? dinv[r0 + 3] : 1.f;
        if (ACC) {
            Y[(r0 + 0) * FOUT + t] += a0 * s0;
            Y[(r0 + 1) * FOUT + t] += a1 * s1;
            Y[(r0 + 2) * FOUT + t] += a2 * s2;
            Y[(r0 + 3) * FOUT + t] += a3 * s3;
        } else {
            Y[(r0 + 0) * FOUT + t] = a0 * s0;
            Y[(r0 + 1) * FOUT + t] = a1 * s1;
            Y[(r0 + 2) * FOUT + t] = a2 * s2;
            Y[(r0 + 3) * FOUT + t] = a3 * s3;
        }
    }
}

// ---------------- zero ------------------------------------------------------
__global__ void k_zero(float* __restrict__ p, int n4) {
    int i = blockIdx.x * blockDim.x + threadIdx.x;
    if (i < n4) ((float4*)p)[i] = make_float4(0.f, 0.f, 0.f, 0.f);
}

// ---------------- scatter: agg[dst] += y'[src] (warp-coalesced rows) --------
template <int F>
__global__ void k_scatter(const int* __restrict__ src, const int* __restrict__ dst,
                          const float* __restrict__ y, float* __restrict__ agg) {
    long long tid = (long long)blockIdx.x * blockDim.x + threadIdx.x;
    int e = (int)(tid / (F / 4));
    int f = (int)(tid % (F / 4)) * 4;
    if (e >= EE) return;
    int s = __ldg(&src[e]);
    int d = __ldg(&dst[e]);
    float4 v = *(const float4*)&y[(long long)s * F + f];
    float* a = &agg[(long long)d * F + f];
    atomicAdd(a + 0, v.x);
    atomicAdd(a + 1, v.y);
    atomicAdd(a + 2, v.z);
    atomicAdd(a + 3, v.w);
}

// ---------------- finalize: out = silu(dinv*(agg+y') + b) -------------------
template <int F>
__global__ void k_finalize(const float* __restrict__ agg, const float* __restrict__ y,
                           const float* __restrict__ dinv, const float* __restrict__ b,
                           float* __restrict__ out) {
    int idx = blockIdx.x * blockDim.x + threadIdx.x;
    if (idx >= NN * (F / 4)) return;
    int node = idx / (F / 4);
    int f4 = idx % (F / 4);
    float di = dinv[node];
    float4 av = ((const float4*)agg)[idx];
    float4 yv = ((const float4*)y)[idx];
    float4 bv = ((const float4*)b)[f4];
    float v0 = di * (av.x + yv.x) + bv.x;
    float v1 = di * (av.y + yv.y) + bv.y;
    float v2 = di * (av.z + yv.z) + bv.z;
    float v3 = di * (av.w + yv.w) + bv.w;
    float4 o;
    o.x = v0 / (1.0f + expf(-v0));
    o.y = v1 / (1.0f + expf(-v1));
    o.z = v2 / (1.0f + expf(-v2));
    o.w = v3 / (1.0f + expf(-v3));
    ((float4*)out)[idx] = o;
}

// ---------------- launch ----------------------------------------------------
extern "C" void kernel_launch(void* const* d_in, const int* in_sizes, int n_in,
                              void* d_out, int out_size) {
    const float* noise_x   = (const float*)d_in[0];
    const int*   edge      = (const int*)d_in[1];
    const int*   t_in      = (const int*)d_in[2];
    const int*   train_anm = (const int*)d_in[3];
    const int*   train_nrm = (const int*)d_in[4];
    const float* time_w1   = (const float*)d_in[5];
    const float* time_b1   = (const float*)d_in[6];
    const float* time_w2   = (const float*)d_in[7];
    const float* time_b2   = (const float*)d_in[8];
    const float* label_emb = (const float*)d_in[9];
    const float* w0 = (const float*)d_in[10];
    const float* b0 = (const float*)d_in[11];
    const float* w1 = (const float*)d_in[12];
    const float* b1 = (const float*)d_in[13];
    const float* w2 = (const float*)d_in[14];
    const float* b2 = (const float*)d_in[15];
    const float* w3 = (const float*)d_in[16];
    const float* b3 = (const float*)d_in[17];
    float* out = (float*)d_out;

    const int* src = edge;
    const int* dst = edge + EE;
    int n_anm = in_sizes[3];
    int n_nrm = in_sizes[4];

    float *p_dinv, *p_temb, *p_xt, *p_y, *p_agg, *p_h0, *p_h1, *p_h2;
    int *p_deg, *p_flag;
    cudaGetSymbolAddress((void**)&p_dinv, g_dinv);
    cudaGetSymbolAddress((void**)&p_temb, g_temb);
    cudaGetSymbolAddress((void**)&p_xt,   g_xt);
    cudaGetSymbolAddress((void**)&p_y,    g_y);
    cudaGetSymbolAddress((void**)&p_agg,  g_agg);
    cudaGetSymbolAddress((void**)&p_h0,   g_h0);
    cudaGetSymbolAddress((void**)&p_h1,   g_h1);
    cudaGetSymbolAddress((void**)&p_h2,   g_h2);
    cudaGetSymbolAddress((void**)&p_deg,  g_deg);
    cudaGetSymbolAddress((void**)&p_flag, g_flag);

    const int TB = 256;
    k_init<<<(NN + TB - 1) / TB, TB>>>(p_deg, p_flag);
    k_deg<<<(EE + TB - 1) / TB, TB>>>(dst, p_deg);
    k_flag<<<(n_anm + TB - 1) / TB, TB>>>(train_anm, n_anm, 1, p_flag);
    k_flag<<<(n_nrm + TB - 1) / TB, TB>>>(train_nrm, n_nrm, 2, p_flag);
    k_temb<<<1, DD>>>(t_in, time_w1, time_b1, time_w2, time_b2, p_temb);
    k_dinv<<<(NN + TB - 1) / TB, TB>>>(p_deg, p_dinv);
    k_xt<<<(NN * (DD / 4) + TB - 1) / TB, TB>>>(noise_x, label_emb, p_temb, p_flag, p_xt);

    // ---- layer 0: x_t[N,64] @ w0[64,128] -> h0 (silu) ----
    k_gemm<64, 128, false, true><<<NN / 8, 128>>>(p_xt, w0, p_y, p_dinv);
    k_zero<<<(NN * GG / 4 + TB - 1) / TB, TB>>>(p_agg, NN * GG / 4);
    k_scatter<128><<<(int)(((long long)EE * 32 + TB - 1) / TB), TB>>>(src, dst, p_y, p_agg);
    k_finalize<128><<<(NN * 32 + TB - 1) / TB, TB>>>(p_agg, p_y, p_dinv, b0, p_h0);

    // ---- layer 1: h0[N,128] @ w1[128,64] -> h1 (silu) ----
    k_gemm<128, 64, false, true><<<NN / 8, 64>>>(p_h0, w1, p_y, p_dinv);
    k_zero<<<(NN * 64 / 4 + TB - 1) / TB, TB>>>(p_agg, NN * 64 / 4);
    k_scatter<64><<<(int)(((long long)EE * 16 + TB - 1) / TB), TB>>>(src, dst, p_y, p_agg);
    k_finalize<64><<<(NN * 16 + TB - 1) / TB, TB>>>(p_agg, p_y, p_dinv, b1, p_h1);

    // ---- layer 2: h1[N,64] @ w2[64,128] -> h2 (silu) ----
    k_gemm<64, 128, false, true><<<NN / 8, 128>>>(p_h1, w2, p_y, p_dinv);
    k_zero<<<(NN * GG / 4 + TB - 1) / TB, TB>>>(p_agg, NN * GG / 4);
    k_scatter<128><<<(int)(((long long)EE * 32 + TB - 1) / TB), TB>>>(src, dst, p_y, p_agg);
    k_finalize<128><<<(NN * 32 + TB - 1) / TB, TB>>>(p_agg, p_y, p_dinv, b2, p_h2);

    // ---- layer 3: concat(h2,h0)[N,256] @ w3[256,64] -> out (silu) ----
    k_gemm<128, 64, false, true><<<NN / 8, 64>>>(p_h2, w3, p_y, p_dinv);
    k_gemm<128, 64, true,  true><<<NN / 8, 64>>>(p_h0, w3 + 128 * 64, p_y, p_dinv);
    k_zero<<<(NN * 64 / 4 + TB - 1) / TB, TB>>>(p_agg, NN * 64 / 4);
    k_scatter<64><<<(int)(((long long)EE * 16 + TB - 1) / TB), TB>>>(src, dst, p_y, p_agg);
    k_finalize<64><<<(NN * 16 + TB - 1) / TB, TB>>>(p_agg, p_y, p_dinv, b3, out);
}

// round 2
// speedup vs baseline: 2.3560x; 2.3560x over previous
#include <cuda_runtime.h>
#include <math.h>

#define NN 100000
#define EE 1000000
#define DD 64
#define GG 128

// ---------------- scratch (device globals; no allocation allowed) ------------
__device__ float g_dinv[NN];
__device__ int   g_deg[NN];
__device__ int   g_flag[NN];
__device__ float g_temb[DD];
__device__ float g_xt[NN * DD];
__device__ float g_y[NN * GG];     // per-layer (xW)*dinv
__device__ float g_agg[NN * GG];   // per-layer edge aggregate
__device__ float g_h0[NN * GG];
__device__ float g_h1[NN * (GG / 2)];
__device__ float g_h2[NN * GG];

// ---------------- small kernels ---------------------------------------------
__global__ void k_init(int* deg, int* flag) {
    int i = blockIdx.x * blockDim.x + threadIdx.x;
    if (i < NN) { deg[i] = 0; flag[i] = 0; }
}

__global__ void k_deg(const int* __restrict__ dst, int* deg) {
    int e = blockIdx.x * blockDim.x + threadIdx.x;
    if (e < EE) atomicAdd(&deg[dst[e]], 1);
}

__global__ void k_flag(const int* __restrict__ idx, int n, int val, int* flag) {
    int i = blockIdx.x * blockDim.x + threadIdx.x;
    if (i < n) flag[idx[i]] = val;
}

// time-embedding MLP: one block, 64 threads
__global__ void k_temb(const int* __restrict__ t,
                       const float* __restrict__ w1, const float* __restrict__ b1,
                       const float* __restrict__ w2, const float* __restrict__ b2,
                       float* temb) {
    __shared__ float emb[DD];
    __shared__ float h[DD];
    int j = threadIdx.x;
    float tv = (float)t[0];
    if (j < 32) {
        float freq = expf((float)j * (-logf(10000.0f) / 31.0f));
        float arg = tv * freq;
        emb[j] = sinf(arg);
        emb[j + 32] = cosf(arg);
    }
    __syncthreads();
    float acc = b1[j];
    #pragma unroll
    for (int k = 0; k < DD; k++) acc += emb[k] * w1[k * DD + j];
    acc = acc / (1.0f + expf(-acc));   // silu
    h[j] = acc;
    __syncthreads();
    float acc2 = b2[j];
    #pragma unroll
    for (int k = 0; k < DD; k++) acc2 += h[k] * w2[k * DD + j];
    temb[j] = acc2;
}

__global__ void k_dinv(const int* __restrict__ deg, float* dinv) {
    int i = blockIdx.x * blockDim.x + threadIdx.x;
    if (i < NN) dinv[i] = rsqrtf((float)deg[i] + 1.0f);
}

// x_t = noise_x + temb + label
__global__ void k_xt(const float* __restrict__ noise_x,
                     const float* __restrict__ label_emb,
                     const float* __restrict__ temb,
                     const int* __restrict__ flag,
                     float* __restrict__ xt) {
    int idx = blockIdx.x * blockDim.x + threadIdx.x;
    if (idx >= NN * (DD / 4)) return;
    int node = idx / (DD / 4);
    int f4 = idx % (DD / 4);
    float4 v = ((const float4*)noise_x)[idx];
    float4 tb = ((const float4*)temb)[f4];
    v.x += tb.x; v.y += tb.y; v.z += tb.z; v.w += tb.w;
    int fl = flag[node];
    if (fl == 1) {
        float4 l = ((const float4*)(label_emb + DD))[f4];
        v.x += l.x; v.y += l.y; v.z += l.z; v.w += l.w;
    } else if (fl == 2) {
        float4 l = ((const float4*)label_emb)[f4];
        v.x += l.x; v.y += l.y; v.z += l.z; v.w += l.w;
    }
    ((float4*)xt)[idx] = v;
}

// ---------------- register-blocked GEMM --------------------------------------
// Y[r, c] (+)= (sum_k X[r,k] * W[k,c]) * dinv[r]
// 128 threads, 8x8 per-thread micro-tile. BM=64 (FOUT=128) or 128 (FOUT=64).
template <int FIN, int FOUT, bool ACC>
__global__ void __launch_bounds__(128) k_gemm(const float* __restrict__ X,
                                              const float* __restrict__ Wg,
                                              float* __restrict__ Y,
                                              const float* __restrict__ dinv) {
    constexpr int BM = (FOUT == 128) ? 64 : 128;
    constexpr int BK = 16;
    constexpr int CT = FOUT / 8;       // 16 or 8 column-threads
    constexpr int XP = BM + 4;         // padded X row length (floats)
    __shared__ float Ws[FIN * FOUT];
    __shared__ float Xs[BK][XP];

    int tid = threadIdx.x;
    #pragma unroll 4
    for (int i = tid; i < FIN * FOUT; i += 128) Ws[i] = Wg[i];

    int ct = tid % CT;
    int rt = tid / CT;
    int c0 = ct * 8;
    int r0 = rt * 8;
    int base = blockIdx.x * BM;

    float acc[8][8];
    #pragma unroll
    for (int i = 0; i < 8; i++)
        #pragma unroll
        for (int j = 0; j < 8; j++) acc[i][j] = 0.f;

    for (int kc = 0; kc < FIN; kc += BK) {
        __syncthreads();
        // load Xs transposed: Xs[k][r] = X[base+r][kc+k]
        #pragma unroll
        for (int i = 0; i < BM * BK / 128; i++) {
            int idx = i * 128 + tid;
            int k = idx % BK, r = idx / BK;
            int gr = base + r;
            if (gr >= NN) gr = NN - 1;
            Xs[k][r] = X[(long long)gr * FIN + kc + k];
        }
        __syncthreads();
        #pragma unroll
        for (int k = 0; k < BK; k++) {
            float4 w0 = *(const float4*)&Ws[(kc + k) * FOUT + c0];
            float4 w1 = *(const float4*)&Ws[(kc + k) * FOUT + c0 + 4];
            float4 x0 = *(const float4*)&Xs[k][r0];
            float4 x1 = *(const float4*)&Xs[k][r0 + 4];
            float xr[8] = {x0.x, x0.y, x0.z, x0.w, x1.x, x1.y, x1.z, x1.w};
            float wc[8] = {w0.x, w0.y, w0.z, w0.w, w1.x, w1.y, w1.z, w1.w};
            #pragma unroll
            for (int i = 0; i < 8; i++)
                #pragma unroll
                for (int j = 0; j < 8; j++)
                    acc[i][j] += xr[i] * wc[j];
        }
    }

    #pragma unroll
    for (int i = 0; i < 8; i++) {
        int gr = base + r0 + i;
        if (gr >= NN) break;
        float s = dinv[gr];
        float* yp = &Y[(long long)gr * FOUT + c0];
        if (ACC) {
            float4 o0 = *(float4*)yp;
            float4 o1 = *(float4*)(yp + 4);
            o0.x += acc[i][0] * s; o0.y += acc[i][1] * s;
            o0.z += acc[i][2] * s; o0.w += acc[i][3] * s;
            o1.x += acc[i][4] * s; o1.y += acc[i][5] * s;
            o1.z += acc[i][6] * s; o1.w += acc[i][7] * s;
            *(float4*)yp = o0;
            *(float4*)(yp + 4) = o1;
        } else {
            float4 o0 = make_float4(acc[i][0] * s, acc[i][1] * s, acc[i][2] * s, acc[i][3] * s);
            float4 o1 = make_float4(acc[i][4] * s, acc[i][5] * s, acc[i][6] * s, acc[i][7] * s);
            *(float4*)yp = o0;
            *(float4*)(yp + 4) = o1;
        }
    }
}

// ---------------- zero ------------------------------------------------------
__global__ void k_zero(float* __restrict__ p, int n4) {
    int i = blockIdx.x * blockDim.x + threadIdx.x;
    if (i < n4) ((float4*)p)[i] = make_float4(0.f, 0.f, 0.f, 0.f);
}

// ---------------- scatter: agg[dst] += y'[src] with vector red ---------------
__device__ __forceinline__ void red_add_v4(float* p, float4 v) {
    asm volatile("red.global.add.v4.f32 [%0], {%1,%2,%3,%4};"
                 :: "l"(p), "f"(v.x), "f"(v.y), "f"(v.z), "f"(v.w)
                 : "memory");
}

template <int F>
__global__ void k_scatter(const int* __restrict__ src, const int* __restrict__ dst,
                          const float* __restrict__ y, float* __restrict__ agg) {
    long long tid = (long long)blockIdx.x * blockDim.x + threadIdx.x;
    int e = (int)(tid / (F / 4));
    int f = (int)(tid % (F / 4)) * 4;
    if (e >= EE) return;
    int s = __ldg(&src[e]);
    int d = __ldg(&dst[e]);
    float4 v = *(const float4*)&y[(long long)s * F + f];
    red_add_v4(&agg[(long long)d * F + f], v);
}

// ---------------- finalize: out = silu(dinv*(agg+y') + b) -------------------
template <int F>
__global__ void k_finalize(const float* __restrict__ agg, const float* __restrict__ y,
                           const float* __restrict__ dinv, const float* __restrict__ b,
                           float* __restrict__ out) {
    int idx = blockIdx.x * blockDim.x + threadIdx.x;
    if (idx >= NN * (F / 4)) return;
    int node = idx / (F / 4);
    int f4 = idx % (F / 4);
    float di = dinv[node];
    float4 av = ((const float4*)agg)[idx];
    float4 yv = ((const float4*)y)[idx];
    float4 bv = ((const float4*)b)[f4];
    float v0 = di * (av.x + yv.x) + bv.x;
    float v1 = di * (av.y + yv.y) + bv.y;
    float v2 = di * (av.z + yv.z) + bv.z;
    float v3 = di * (av.w + yv.w) + bv.w;
    float4 o;
    o.x = v0 / (1.0f + expf(-v0));
    o.y = v1 / (1.0f + expf(-v1));
    o.z = v2 / (1.0f + expf(-v2));
    o.w = v3 / (1.0f + expf(-v3));
    ((float4*)out)[idx] = o;
}

// ---------------- launch ----------------------------------------------------
extern "C" void kernel_launch(void* const* d_in, const int* in_sizes, int n_in,
                              void* d_out, int out_size) {
    const float* noise_x   = (const float*)d_in[0];
    const int*   edge      = (const int*)d_in[1];
    const int*   t_in      = (const int*)d_in[2];
    const int*   train_anm = (const int*)d_in[3];
    const int*   train_nrm = (const int*)d_in[4];
    const float* time_w1   = (const float*)d_in[5];
    const float* time_b1   = (const float*)d_in[6];
    const float* time_w2   = (const float*)d_in[7];
    const float* time_b2   = (const float*)d_in[8];
    const float* label_emb = (const float*)d_in[9];
    const float* w0 = (const float*)d_in[10];
    const float* b0 = (const float*)d_in[11];
    const float* w1 = (const float*)d_in[12];
    const float* b1 = (const float*)d_in[13];
    const float* w2 = (const float*)d_in[14];
    const float* b2 = (const float*)d_in[15];
    const float* w3 = (const float*)d_in[16];
    const float* b3 = (const float*)d_in[17];
    float* out = (float*)d_out;

    const int* src = edge;
    const int* dst = edge + EE;
    int n_anm = in_sizes[3];
    int n_nrm = in_sizes[4];

    float *p_dinv, *p_temb, *p_xt, *p_y, *p_agg, *p_h0, *p_h1, *p_h2;
    int *p_deg, *p_flag;
    cudaGetSymbolAddress((void**)&p_dinv, g_dinv);
    cudaGetSymbolAddress((void**)&p_temb, g_temb);
    cudaGetSymbolAddress((void**)&p_xt,   g_xt);
    cudaGetSymbolAddress((void**)&p_y,    g_y);
    cudaGetSymbolAddress((void**)&p_agg,  g_agg);
    cudaGetSymbolAddress((void**)&p_h0,   g_h0);
    cudaGetSymbolAddress((void**)&p_h1,   g_h1);
    cudaGetSymbolAddress((void**)&p_h2,   g_h2);
    cudaGetSymbolAddress((void**)&p_deg,  g_deg);
    cudaGetSymbolAddress((void**)&p_flag, g_flag);

    const int TB = 256;
    const int GB64  = (NN + 63) / 64;    // blocks for BM=64 (FOUT=128)
    const int GB128 = (NN + 127) / 128;  // blocks for BM=128 (FOUT=64)

    k_init<<<(NN + TB - 1) / TB, TB>>>(p_deg, p_flag);
    k_deg<<<(EE + TB - 1) / TB, TB>>>(dst, p_deg);
    k_flag<<<(n_anm + TB - 1) / TB, TB>>>(train_anm, n_anm, 1, p_flag);
    k_flag<<<(n_nrm + TB - 1) / TB, TB>>>(train_nrm, n_nrm, 2, p_flag);
    k_temb<<<1, DD>>>(t_in, time_w1, time_b1, time_w2, time_b2, p_temb);
    k_dinv<<<(NN + TB - 1) / TB, TB>>>(p_deg, p_dinv);
    k_xt<<<(NN * (DD / 4) + TB - 1) / TB, TB>>>(noise_x, label_emb, p_temb, p_flag, p_xt);

    // ---- layer 0: x_t[N,64] @ w0[64,128] -> h0 (silu) ----
    k_gemm<64, 128, false><<<GB64, 128>>>(p_xt, w0, p_y, p_dinv);
    k_zero<<<(NN * GG / 4 + TB - 1) / TB, TB>>>(p_agg, NN * GG / 4);
    k_scatter<128><<<(int)(((long long)EE * 32 + TB - 1) / TB), TB>>>(src, dst, p_y, p_agg);
    k_finalize<128><<<(NN * 32 + TB - 1) / TB, TB>>>(p_agg, p_y, p_dinv, b0, p_h0);

    // ---- layer 1: h0[N,128] @ w1[128,64] -> h1 (silu) ----
    k_gemm<128, 64, false><<<GB128, 128>>>(p_h0, w1, p_y, p_dinv);
    k_zero<<<(NN * 64 / 4 + TB - 1) / TB, TB>>>(p_agg, NN * 64 / 4);
    k_scatter<64><<<(int)(((long long)EE * 16 + TB - 1) / TB), TB>>>(src, dst, p_y, p_agg);
    k_finalize<64><<<(NN * 16 + TB - 1) / TB, TB>>>(p_agg, p_y, p_dinv, b1, p_h1);

    // ---- layer 2: h1[N,64] @ w2[64,128] -> h2 (silu) ----
    k_gemm<64, 128, false><<<GB64, 128>>>(p_h1, w2, p_y, p_dinv);
    k_zero<<<(NN * GG / 4 + TB - 1) / TB, TB>>>(p_agg, NN * GG / 4);
    k_scatter<128><<<(int)(((long long)EE * 32 + TB - 1) / TB), TB>>>(src, dst, p_y, p_agg);
    k_finalize<128><<<(NN * 32 + TB - 1) / TB, TB>>>(p_agg, p_y, p_dinv, b2, p_h2);

    // ---- layer 3: concat(h2,h0)[N,256] @ w3[256,64] -> out (silu) ----
    k_gemm<128, 64, false><<<GB128, 128>>>(p_h2, w3, p_y, p_dinv);
    k_gemm<128, 64, true><<<GB128, 128>>>(p_h0, w3 + 128 * 64, p_y, p_dinv);
    k_zero<<<(NN * 64 / 4 + TB - 1) / TB, TB>>>(p_agg, NN * 64 / 4);
    k_scatter<64><<<(int)(((long long)EE * 16 + TB - 1) / TB), TB>>>(src, dst, p_y, p_agg);
    k_finalize<64><<<(NN * 16 + TB - 1) / TB, TB>>>(p_agg, p_y, p_dinv, b3, out);
}

// round 3
// speedup vs baseline: 3.2241x; 1.3685x over previous
#include <cuda_runtime.h>
#include <math.h>

#define NN 100000
#define EE 1000000
#define DD 64
#define GG 128
#define SB 512
#define NB ((NN + SB - 1) / SB)

// ---------------- scratch (device globals) -----------------------------------
__device__ float g_dinv[NN];
__device__ int   g_deg[NN];
__device__ int   g_flag[NN];
__device__ float g_temb[DD];
__device__ float g_y[NN * GG];
__device__ float g_h0[NN * GG];
__device__ float g_h1[NN * (GG / 2)];
__device__ float g_h2[NN * GG];
__device__ int   g_off[NN + 1];
__device__ int   g_bsum[NB + 1];
__device__ int   g_cur[NN];
__device__ int   g_csr[EE];

// ---------------- small kernels ---------------------------------------------
__global__ void k_init(int* deg, int* flag) {
    int i = blockIdx.x * blockDim.x + threadIdx.x;
    if (i < NN) { deg[i] = 0; flag[i] = 0; }
}

__global__ void k_deg(const int* __restrict__ dst, int* deg) {
    int e = blockIdx.x * blockDim.x + threadIdx.x;
    if (e < EE) atomicAdd(&deg[dst[e]], 1);
}

// anm -> 1, norm -> 2; norm has priority (reference sets anm first, norm last)
__global__ void k_flags(const int* __restrict__ anm, int n_anm,
                        const int* __restrict__ nrm, int n_nrm, int* flag) {
    int i = blockIdx.x * blockDim.x + threadIdx.x;
    if (i < n_anm) atomicMax(&flag[anm[i]], 1);
    if (i < n_nrm) atomicMax(&flag[nrm[i]], 2);
}

__global__ void k_temb(const int* __restrict__ t,
                       const float* __restrict__ w1, const float* __restrict__ b1,
                       const float* __restrict__ w2, const float* __restrict__ b2,
                       float* temb) {
    __shared__ float emb[DD];
    __shared__ float h[DD];
    int j = threadIdx.x;
    float tv = (float)t[0];
    if (j < 32) {
        float freq = expf((float)j * (-logf(10000.0f) / 31.0f));
        float arg = tv * freq;
        emb[j] = sinf(arg);
        emb[j + 32] = cosf(arg);
    }
    __syncthreads();
    float acc = b1[j];
    #pragma unroll
    for (int k = 0; k < DD; k++) acc += emb[k] * w1[k * DD + j];
    acc = acc / (1.0f + expf(-acc));
    h[j] = acc;
    __syncthreads();
    float acc2 = b2[j];
    #pragma unroll
    for (int k = 0; k < DD; k++) acc2 += h[k] * w2[k * DD + j];
    temb[j] = acc2;
}

__global__ void k_dinv(const int* __restrict__ deg, float* dinv) {
    int i = blockIdx.x * blockDim.x + threadIdx.x;
    if (i < NN) dinv[i] = rsqrtf((float)deg[i] + 1.0f);
}

// ---------------- CSR build: prefix scan + fill ------------------------------
__global__ void k_scan1(const int* __restrict__ deg, int* off, int* bsum) {
    __shared__ int sh[SB];
    int i = blockIdx.x * SB + threadIdx.x;
    int v = (i < NN) ? deg[i] : 0;
    sh[threadIdx.x] = v;
    __syncthreads();
    for (int s = 1; s < SB; s <<= 1) {
        int t = (threadIdx.x >= s) ? sh[threadIdx.x - s] : 0;
        __syncthreads();
        sh[threadIdx.x] += t;
        __syncthreads();
    }
    if (i < NN) off[i] = sh[threadIdx.x] - v;   // exclusive
    if (threadIdx.x == SB - 1) bsum[blockIdx.x] = sh[SB - 1];
}

__global__ void k_scan2(int* bsum) {
    if (threadIdx.x == 0) {
        int acc = 0;
        for (int b = 0; b < NB; b++) { int t = bsum[b]; bsum[b] = acc; acc += t; }
    }
}

__global__ void k_scan3(int* off, const int* __restrict__ bsum, int* cur) {
    int i = blockIdx.x * blockDim.x + threadIdx.x;
    if (i < NN) { off[i] += bsum[i / SB]; cur[i] = 0; }
    if (i == 0) off[NN] = EE;
}

__global__ void k_fill(const int* __restrict__ src, const int* __restrict__ dst,
                       const int* __restrict__ off, int* cur, int* csr) {
    int e = blockIdx.x * blockDim.x + threadIdx.x;
    if (e < EE) {
        int d = dst[e];
        int p = off[d] + atomicAdd(&cur[d], 1);
        csr[p] = src[e];
    }
}

// ---------------- GEMM-0: fused x_t construction, FIN=64 FOUT=128 ------------
// Y[r,c] = (sum_k (noise[r,k]+temb[k]+lab[r,k]) * W[k,c]) * dinv[r]
__global__ void __launch_bounds__(128) k_gemm0(const float* __restrict__ noise,
                                               const float* __restrict__ lemb,
                                               const float* __restrict__ temb,
                                               const int* __restrict__ flag,
                                               const float* __restrict__ Wg,
                                               float* __restrict__ Y,
                                               const float* __restrict__ dinv) {
    constexpr int FIN = 64, FOUT = 128, BM = 64, BK = 16, XP = BM + 4;
    __shared__ float Ws[FIN * FOUT];
    __shared__ float Xs[BK][XP];
    __shared__ float temb_s[FIN], l0_s[FIN], l1_s[FIN];
    __shared__ int   flags_s[BM];

    int tid = threadIdx.x;
    #pragma unroll 4
    for (int i = tid; i < FIN * FOUT; i += 128) Ws[i] = Wg[i];
    int base = blockIdx.x * BM;
    if (tid < FIN) {
        temb_s[tid] = temb[tid];
        l0_s[tid] = lemb[tid];
        l1_s[tid] = lemb[FIN + tid];
    }
    if (tid < BM) {
        int gr = base + tid; if (gr >= NN) gr = NN - 1;
        flags_s[tid] = flag[gr];
    }

    int ct = tid % 16, rt = tid / 16;
    int c0 = ct * 8, r0 = rt * 8;

    float acc[8][8];
    #pragma unroll
    for (int i = 0; i < 8; i++)
        #pragma unroll
        for (int j = 0; j < 8; j++) acc[i][j] = 0.f;

    for (int kc = 0; kc < FIN; kc += BK) {
        __syncthreads();
        #pragma unroll
        for (int i = 0; i < BM * BK / 128; i++) {
            int idx = i * 128 + tid;
            int k = idx % BK, r = idx / BK;
            int gr = base + r; if (gr >= NN) gr = NN - 1;
            int kk = kc + k;
            float v = noise[(long long)gr * FIN + kk] + temb_s[kk];
            int fl = flags_s[r];
            if (fl == 1) v += l1_s[kk];
            else if (fl == 2) v += l0_s[kk];
            Xs[k][r] = v;
        }
        __syncthreads();
        #pragma unroll
        for (int k = 0; k < BK; k++) {
            float4 w0 = *(const float4*)&Ws[(kc + k) * FOUT + c0];
            float4 w1 = *(const float4*)&Ws[(kc + k) * FOUT + c0 + 4];
            float4 x0 = *(const float4*)&Xs[k][r0];
            float4 x1 = *(const float4*)&Xs[k][r0 + 4];
            float xr[8] = {x0.x, x0.y, x0.z, x0.w, x1.x, x1.y, x1.z, x1.w};
            float wc[8] = {w0.x, w0.y, w0.z, w0.w, w1.x, w1.y, w1.z, w1.w};
            #pragma unroll
            for (int i = 0; i < 8; i++)
                #pragma unroll
                for (int j = 0; j < 8; j++)
                    acc[i][j] += xr[i] * wc[j];
        }
    }

    #pragma unroll
    for (int i = 0; i < 8; i++) {
        int gr = base + r0 + i;
        if (gr >= NN) break;
        float s = dinv[gr];
        float* yp = &Y[(long long)gr * FOUT + c0];
        *(float4*)yp = make_float4(acc[i][0] * s, acc[i][1] * s, acc[i][2] * s, acc[i][3] * s);
        *(float4*)(yp + 4) = make_float4(acc[i][4] * s, acc[i][5] * s, acc[i][6] * s, acc[i][7] * s);
    }
}

// ---------------- generic register-blocked GEMM ------------------------------
template <int FIN, int FOUT, bool ACC>
__global__ void __launch_bounds__(128) k_gemm(const float* __restrict__ X,
                                              const float* __restrict__ Wg,
                                              float* __restrict__ Y,
                                              const float* __restrict__ dinv) {
    constexpr int BM = (FOUT == 128) ? 64 : 128;
    constexpr int BK = 16;
    constexpr int CT = FOUT / 8;
    constexpr int XP = BM + 4;
    __shared__ float Ws[FIN * FOUT];
    __shared__ float Xs[BK][XP];

    int tid = threadIdx.x;
    #pragma unroll 4
    for (int i = tid; i < FIN * FOUT; i += 128) Ws[i] = Wg[i];

    int ct = tid % CT, rt = tid / CT;
    int c0 = ct * 8, r0 = rt * 8;
    int base = blockIdx.x * BM;

    float acc[8][8];
    #pragma unroll
    for (int i = 0; i < 8; i++)
        #pragma unroll
        for (int j = 0; j < 8; j++) acc[i][j] = 0.f;

    for (int kc = 0; kc < FIN; kc += BK) {
        __syncthreads();
        #pragma unroll
        for (int i = 0; i < BM * BK / 128; i++) {
            int idx = i * 128 + tid;
            int k = idx % BK, r = idx / BK;
            int gr = base + r;
            if (gr >= NN) gr = NN - 1;
            Xs[k][r] = X[(long long)gr * FIN + kc + k];
        }
        __syncthreads();
        #pragma unroll
        for (int k = 0; k < BK; k++) {
            float4 w0 = *(const float4*)&Ws[(kc + k) * FOUT + c0];
            float4 w1 = *(const float4*)&Ws[(kc + k) * FOUT + c0 + 4];
            float4 x0 = *(const float4*)&Xs[k][r0];
            float4 x1 = *(const float4*)&Xs[k][r0 + 4];
            float xr[8] = {x0.x, x0.y, x0.z, x0.w, x1.x, x1.y, x1.z, x1.w};
            float wc[8] = {w0.x, w0.y, w0.z, w0.w, w1.x, w1.y, w1.z, w1.w};
            #pragma unroll
            for (int i = 0; i < 8; i++)
                #pragma unroll
                for (int j = 0; j < 8; j++)
                    acc[i][j] += xr[i] * wc[j];
        }
    }

    #pragma unroll
    for (int i = 0; i < 8; i++) {
        int gr = base + r0 + i;
        if (gr >= NN) break;
        float s = dinv[gr];
        float* yp = &Y[(long long)gr * FOUT + c0];
        if (ACC) {
            float4 o0 = *(float4*)yp;
            float4 o1 = *(float4*)(yp + 4);
            o0.x += acc[i][0] * s; o0.y += acc[i][1] * s;
            o0.z += acc[i][2] * s; o0.w += acc[i][3] * s;
            o1.x += acc[i][4] * s; o1.y += acc[i][5] * s;
            o1.z += acc[i][6] * s; o1.w += acc[i][7] * s;
            *(float4*)yp = o0;
            *(float4*)(yp + 4) = o1;
        } else {
            *(float4*)yp = make_float4(acc[i][0] * s, acc[i][1] * s, acc[i][2] * s, acc[i][3] * s);
            *(float4*)(yp + 4) = make_float4(acc[i][4] * s, acc[i][5] * s, acc[i][6] * s, acc[i][7] * s);
        }
    }
}

// ---------------- gather: out = silu(dinv*(sum_in y[src] + y[i]) + b) --------
template <int F>
__global__ void __launch_bounds__(256) k_gather(const float* __restrict__ y,
                                                const int* __restrict__ off,
                                                const int* __restrict__ csr,
                                                const float* __restrict__ dinv,
                                                const float* __restrict__ b,
                                                float* __restrict__ out) {
    int warp = (blockIdx.x * 256 + threadIdx.x) >> 5;
    int lane = threadIdx.x & 31;
    if (warp >= NN) return;
    int beg = off[warp], end = off[warp + 1];
    constexpr int V = F / 32;
    float acc[V];
    {
        const float* yr = y + (long long)warp * F + lane * V;
        if constexpr (V == 4) {
            float4 t = *(const float4*)yr;
            acc[0] = t.x; acc[1] = t.y; acc[2] = t.z; acc[3] = t.w;
        } else {
            float2 t = *(const float2*)yr;
            acc[0] = t.x; acc[1] = t.y;
        }
    }
    for (int eb = beg; eb < end; eb += 32) {
        int n = end - eb; if (n > 32) n = 32;
        int s = (lane < n) ? __ldg(&csr[eb + lane]) : 0;
        for (int j = 0; j < n; j++) {
            int sj = __shfl_sync(0xffffffffu, s, j);
            const float* yr = y + (long long)sj * F + lane * V;
            if constexpr (V == 4) {
                float4 t = *(const float4*)yr;
                acc[0] += t.x; acc[1] += t.y; acc[2] += t.z; acc[3] += t.w;
            } else {
                float2 t = *(const float2*)yr;
                acc[0] += t.x; acc[1] += t.y;
            }
        }
    }
    float di = dinv[warp];
    float ov[V];
    #pragma unroll
    for (int v = 0; v < V; v++) {
        float val = di * acc[v] + b[lane * V + v];
        ov[v] = val / (1.0f + expf(-val));
    }
    float* op = out + (long long)warp * F + lane * V;
    if constexpr (V == 4) *(float4*)op = make_float4(ov[0], ov[1], ov[2], ov[3]);
    else *(float2*)op = make_float2(ov[0], ov[1]);
}

// ---------------- launch ----------------------------------------------------
extern "C" void kernel_launch(void* const* d_in, const int* in_sizes, int n_in,
                              void* d_out, int out_size) {
    const float* noise_x   = (const float*)d_in[0];
    const int*   edge      = (const int*)d_in[1];
    const int*   t_in      = (const int*)d_in[2];
    const int*   train_anm = (const int*)d_in[3];
    const int*   train_nrm = (const int*)d_in[4];
    const float* time_w1   = (const float*)d_in[5];
    const float* time_b1   = (const float*)d_in[6];
    const float* time_w2   = (const float*)d_in[7];
    const float* time_b2   = (const float*)d_in[8];
    const float* label_emb = (const float*)d_in[9];
    const float* w0 = (const float*)d_in[10];
    const float* b0 = (const float*)d_in[11];
    const float* w1 = (const float*)d_in[12];
    const float* b1 = (const float*)d_in[13];
    const float* w2 = (const float*)d_in[14];
    const float* b2 = (const float*)d_in[15];
    const float* w3 = (const float*)d_in[16];
    const float* b3 = (const float*)d_in[17];
    float* out = (float*)d_out;

    const int* src = edge;
    const int* dst = edge + EE;
    int n_anm = in_sizes[3];
    int n_nrm = in_sizes[4];
    int n_fl = (n_anm > n_nrm) ? n_anm : n_nrm;

    float *p_dinv, *p_temb, *p_y, *p_h0, *p_h1, *p_h2;
    int *p_deg, *p_flag, *p_off, *p_bsum, *p_cur, *p_csr;
    cudaGetSymbolAddress((void**)&p_dinv, g_dinv);
    cudaGetSymbolAddress((void**)&p_temb, g_temb);
    cudaGetSymbolAddress((void**)&p_y,    g_y);
    cudaGetSymbolAddress((void**)&p_h0,   g_h0);
    cudaGetSymbolAddress((void**)&p_h1,   g_h1);
    cudaGetSymbolAddress((void**)&p_h2,   g_h2);
    cudaGetSymbolAddress((void**)&p_deg,  g_deg);
    cudaGetSymbolAddress((void**)&p_flag, g_flag);
    cudaGetSymbolAddress((void**)&p_off,  g_off);
    cudaGetSymbolAddress((void**)&p_bsum, g_bsum);
    cudaGetSymbolAddress((void**)&p_cur,  g_cur);
    cudaGetSymbolAddress((void**)&p_csr,  g_csr);

    const int TB = 256;
    const int GB64  = (NN + 63) / 64;
    const int GB128 = (NN + 127) / 128;
    const int GGATH = (NN * 32 + TB - 1) / TB;

    // launches 0-4 (setup), launch 5 = k_gemm0 (for ncu -s 5 -c 1)
    k_init<<<(NN + TB - 1) / TB, TB>>>(p_deg, p_flag);
    k_deg<<<(EE + TB - 1) / TB, TB>>>(dst, p_deg);
    k_flags<<<(n_fl + TB - 1) / TB, TB>>>(train_anm, n_anm, train_nrm, n_nrm, p_flag);
    k_temb<<<1, DD>>>(t_in, time_w1, time_b1, time_w2, time_b2, p_temb);
    k_dinv<<<(NN + TB - 1) / TB, TB>>>(p_deg, p_dinv);

    // ---- layer 0 GEMM (fused x_t) ----
    k_gemm0<<<GB64, 128>>>(noise_x, label_emb, p_temb, p_flag, w0, p_y, p_dinv);

    // ---- CSR build ----
    k_scan1<<<NB, SB>>>(p_deg, p_off, p_bsum);
    k_scan2<<<1, 32>>>(p_bsum);
    k_scan3<<<(NN + TB - 1) / TB, TB>>>(p_off, p_bsum, p_cur);
    k_fill<<<(EE + TB - 1) / TB, TB>>>(src, dst, p_off, p_cur, p_csr);

    // ---- layer 0 gather -> h0 ----
    k_gather<128><<<GGATH, TB>>>(p_y, p_off, p_csr, p_dinv, b0, p_h0);

    // ---- layer 1 ----
    k_gemm<128, 64, false><<<GB128, 128>>>(p_h0, w1, p_y, p_dinv);
    k_gather<64><<<GGATH, TB>>>(p_y, p_off, p_csr, p_dinv, b1, p_h1);

    // ---- layer 2 ----
    k_gemm<64, 128, false><<<GB64, 128>>>(p_h1, w2, p_y, p_dinv);
    k_gather<128><<<GGATH, TB>>>(p_y, p_off, p_csr, p_dinv, b2, p_h2);

    // ---- layer 3: concat(h2,h0) @ w3 ----
    k_gemm<128, 64, false><<<GB128, 128>>>(p_h2, w3, p_y, p_dinv);
    k_gemm<128, 64, true><<<GB128, 128>>>(p_h0, w3 + 128 * 64, p_y, p_dinv);
    k_gather<64><<<GGATH, TB>>>(p_y, p_off, p_csr, p_dinv, b3, out);
}